// round 10
// baseline (speedup 1.0000x reference)
#include <cuda_runtime.h>
#include <cstdint>

#define N_MOLS        2000
#define ATOMS_PER_MOL 50
#define N_ATOMS       (N_MOLS * ATOMS_PER_MOL + 1)   // 100001
#define N_BONDS       200001
#define MAX_NB        6
#define ATOM_FDIM     133
#define BOND_FDIM     147
#define HIDDEN        300
#define DEPTH         4
#define H4            (HIDDEN / 4)
#define FB_PAD        148                    // f_bonds cols padded (16B rows)
#define CAT_K         436                    // 300 (amsg) + 133 (f_atoms) + 3 pad
#define CAT4          (CAT_K / 4)            // 109

// ---------------- persistent scratch (device globals; 16B aligned) ----------------
__device__ __align__(16) float g_inp [(size_t)N_BONDS * HIDDEN];
__device__ __align__(16) float g_msgA[(size_t)N_BONDS * HIDDEN];    // ping
__device__ __align__(16) float g_msgB[(size_t)N_BONDS * HIDDEN];    // pong
__device__ __align__(16) float g_amsg[(size_t)N_ATOMS * HIDDEN];
__device__ __align__(16) float g_ah  [(size_t)N_ATOMS * HIDDEN];
__device__ __align__(16) float g_fbt [(size_t)N_BONDS * FB_PAD];    // tf32 f_bonds, padded
__device__ __align__(16) float g_cat [(size_t)N_ATOMS * CAT_K];     // [amsg | tf32 f_atoms | 0]
__device__ __align__(16) float g_Wi  [BOND_FDIM * HIDDEN];          // tf32 weights [K,300]
__device__ __align__(16) float g_Wh  [HIDDEN * HIDDEN];
__device__ __align__(16) float g_WoC [CAT_K * HIDDEN];              // W_o rows permuted to cat order

// ---------------- tf32 helpers ----------------
__device__ __forceinline__ uint32_t f2tf(float x) {
    uint32_t u;
    asm("cvt.rna.tf32.f32 %0, %1;" : "=r"(u) : "f"(x));
    return u;
}
__device__ __forceinline__ float f2tf_f(float x) { return __uint_as_float(f2tf(x)); }

__device__ __forceinline__ void mma_tf32(float* c, const uint32_t* a, const uint32_t* b) {
    asm volatile(
        "mma.sync.aligned.m16n8k8.row.col.f32.tf32.tf32.f32 "
        "{%0,%1,%2,%3}, {%4,%5,%6,%7}, {%8,%9}, {%0,%1,%2,%3};"
        : "+f"(c[0]), "+f"(c[1]), "+f"(c[2]), "+f"(c[3])
        : "r"(a[0]), "r"(a[1]), "r"(a[2]), "r"(a[3]), "r"(b[0]), "r"(b[1]));
}

// ---------------- pre-conversion kernels ----------------
__global__ void cvt_flat(const float* __restrict__ in, float* __restrict__ out, int n) {
    int i = blockIdx.x * blockDim.x + threadIdx.x;
    if (i < n) out[i] = f2tf_f(in[i]);
}
__global__ void cvt_pad(const float* __restrict__ in, float* __restrict__ out,
                        int n, int cin, int cout) {
    int i = blockIdx.x * blockDim.x + threadIdx.x;
    if (i >= n) return;
    int r = i / cout, c = i - r * cout;
    out[i] = (c < cin) ? f2tf_f(in[(size_t)r * cin + c]) : 0.f;
}
// cat cols [300, 436): tf32 f_atoms then zero pad
__global__ void cvt_cat_atoms(const float* __restrict__ fa, float* __restrict__ cat, int n) {
    int i = blockIdx.x * blockDim.x + threadIdx.x;   // n = N_ATOMS * 136
    if (i >= n) return;
    int r = i / 136, c = i - r * 136;
    cat[(size_t)r * CAT_K + HIDDEN + c] =
        (c < ATOM_FDIM) ? f2tf_f(fa[(size_t)r * ATOM_FDIM + c]) : 0.f;
}
// WoC[k'][n]: k'<300 -> W_o[133+k'], k'<433 -> W_o[k'-300], else 0
__global__ void cvt_wo_cat(const float* __restrict__ Wo, float* __restrict__ WoC, int n) {
    int i = blockIdx.x * blockDim.x + threadIdx.x;   // n = CAT_K * 300
    if (i >= n) return;
    int kp = i / HIDDEN, c = i - kp * HIDDEN;
    float v = 0.f;
    if (kp < HIDDEN)                  v = Wo[(size_t)(ATOM_FDIM + kp) * HIDDEN + c];
    else if (kp < HIDDEN + ATOM_FDIM) v = Wo[(size_t)(kp - HIDDEN) * HIDDEN + c];
    WoC[i] = f2tf_f(v);
}

// ---------------- pipelined tf32 tensor-core GEMM, 64x40 warp tiles ----------------
// FUSED=0: A read from memory via cp.async (must be tf32-rounded already).
// FUSED=1: A row b computed on the fly = f2tf(gAm[b2a[b]] - w_bonds[b]*gMs[b2revb[b]]),
//          gathered with float4 LDG, STS'd into the staged A smem. (bond_update fused)
#define TBM 128
#define TBN 160
#define TBK 16
#define STAGES 4
#define AST 20        // A smem k-stride (words): conflict-free, 16B aligned rows
#define BST 168       // B smem n-stride (words): 168 % 32 == 8 -> conflict-free
#define A_WORDS (TBM * AST)   // 2560
#define B_WORDS (TBK * BST)   // 2688
#define SMEM_BYTES (STAGES * (A_WORDS + B_WORDS) * 4)   // 83968

template <int FUSED>
__global__ __launch_bounds__(256, 2) void tgemm300(
    const float* __restrict__ A, int lda,
    const float* __restrict__ B,
    float* __restrict__ C,
    const float* __restrict__ addsrc,
    const float* __restrict__ bias,
    float* __restrict__ rawout,
    int M, int K, int doRelu,
    const float* __restrict__ gAm,      // amsg  [N_ATOMS,300]   (FUSED only)
    const float* __restrict__ gMs,      // msg   [N_BONDS,300]   (FUSED only)
    const int*   __restrict__ b2a,
    const int*   __restrict__ b2revb,
    const float* __restrict__ wB)
{
    extern __shared__ uint32_t sm[];
    uint32_t* sA = sm;
    uint32_t* sB = sm + STAGES * A_WORDS;
    const uint32_t sAaddr = (uint32_t)__cvta_generic_to_shared(sA);
    const uint32_t sBaddr = (uint32_t)__cvta_generic_to_shared(sB);

    const int tid  = threadIdx.x;
    const int lane = tid & 31;
    const int warp = tid >> 5;          // 0..7
    const int g = lane >> 2;
    const int t = lane & 3;
    const int m0w = (warp & 1) * 64;    // 2 warps along M
    const int n0w = (warp >> 1) * 40;   // 4 warps along N

    const int rowBase = blockIdx.y * TBM;
    const int colBase = blockIdx.x * TBN;
    const int nCh = (K + TBK - 1) / TBK;

    // ---- per-thread A-slot geometry: 2 slots of (row, 4-float koff) ----
    const int row0 = tid >> 2,          ko0 = (tid & 3) * 4;
    const int row1 = (256 + tid) >> 2,  ko1 = (tid & 3) * 4;   // rows 64..127
    const int gr0 = rowBase + row0, gr1 = rowBase + row1;

    // fused: load gather indices once
    int ia0 = 0, ir0 = 0, ia1 = 0, ir1 = 0;
    float w0 = 0.f, w1 = 0.f;
    bool v0 = false, v1 = false;
    if (FUSED) {
        v0 = gr0 < M; v1 = gr1 < M;
        if (v0) { ia0 = b2a[gr0]; ir0 = b2revb[gr0]; w0 = wB[gr0]; }
        if (v1) { ia1 = b2a[gr1]; ir1 = b2revb[gr1]; w1 = wB[gr1]; }
    }

    float4 oA0 = make_float4(0.f,0.f,0.f,0.f), oA1 = oA0;
    auto loadA_fused = [&](int c) {
        int gk0 = c * TBK + ko0;
        if (v0 && gk0 < K) {
            float4 u = *reinterpret_cast<const float4*>(gAm + (size_t)ia0 * HIDDEN + gk0);
            float4 m = *reinterpret_cast<const float4*>(gMs + (size_t)ir0 * HIDDEN + gk0);
            oA0.x = f2tf_f(u.x - w0 * m.x); oA0.y = f2tf_f(u.y - w0 * m.y);
            oA0.z = f2tf_f(u.z - w0 * m.z); oA0.w = f2tf_f(u.w - w0 * m.w);
        } else oA0 = make_float4(0.f,0.f,0.f,0.f);
        int gk1 = c * TBK + ko1;
        if (v1 && gk1 < K) {
            float4 u = *reinterpret_cast<const float4*>(gAm + (size_t)ia1 * HIDDEN + gk1);
            float4 m = *reinterpret_cast<const float4*>(gMs + (size_t)ir1 * HIDDEN + gk1);
            oA1.x = f2tf_f(u.x - w1 * m.x); oA1.y = f2tf_f(u.y - w1 * m.y);
            oA1.z = f2tf_f(u.z - w1 * m.z); oA1.w = f2tf_f(u.w - w1 * m.w);
        } else oA1 = make_float4(0.f,0.f,0.f,0.f);
    };
    auto stsA = [&](int c) {
        const int stg = c % STAGES;
        *reinterpret_cast<float4*>(sA + stg * A_WORDS + row0 * AST + ko0) = oA0;
        *reinterpret_cast<float4*>(sA + stg * A_WORDS + row1 * AST + ko1) = oA1;
    };

    auto issue = [&](int c) {
        const int stg = c % STAGES;
        if (FUSED == 0) {
            // A: 128 rows x 16 k = 512 x 16B, 2 chunks/thread (cp.async)
            #pragma unroll
            for (int it = 0; it < 2; it++) {
                int e    = it * 256 + tid;
                int row  = e >> 2;
                int koff = (e & 3) * 4;
                int gr   = rowBase + row;
                int gk   = c * TBK + koff;
                int by   = (gr < M) ? (K - gk) * 4 : 0;
                by = by < 0 ? 0 : (by > 16 ? 16 : by);
                const float* src = by ? (A + (size_t)gr * lda + gk) : A;
                uint32_t dst = sAaddr + (uint32_t)(stg * A_WORDS + row * AST + koff) * 4u;
                asm volatile("cp.async.ca.shared.global [%0], [%1], 16, %2;"
                             :: "r"(dst), "l"(src), "r"(by) : "memory");
            }
        }
        // B: 16 k x 160 n = 640 x 16B
        #pragma unroll
        for (int it = 0; it < 3; it++) {
            int e = it * 256 + tid;
            if (it == 2 && tid >= 128) break;
            int bk  = e / 40;
            int bn4 = (e - bk * 40) * 4;
            int gk  = c * TBK + bk;
            int gn  = colBase + bn4;
            int by  = (gk < K) ? (HIDDEN - gn) * 4 : 0;
            by = by < 0 ? 0 : (by > 16 ? 16 : by);
            const float* src = by ? (B + (size_t)gk * HIDDEN + gn) : B;
            uint32_t dst = sBaddr + (uint32_t)(stg * B_WORDS + bk * BST + bn4) * 4u;
            asm volatile("cp.async.ca.shared.global [%0], [%1], 16, %2;"
                         :: "r"(dst), "l"(src), "r"(by) : "memory");
        }
    };

    float acc[4][5][4];
    #pragma unroll
    for (int i = 0; i < 4; i++)
        #pragma unroll
        for (int j = 0; j < 5; j++)
            #pragma unroll
            for (int q = 0; q < 4; q++) acc[i][j][q] = 0.f;

    if (FUSED) loadA_fused(0);
    #pragma unroll
    for (int s = 0; s < STAGES - 1; s++) {
        if (s < nCh) issue(s);
        asm volatile("cp.async.commit_group;" ::: "memory");
    }

    for (int c = 0; c < nCh; c++) {
        if (FUSED) stsA(c);   // A for chunk c into its stage slot (pre-barrier)
        asm volatile("cp.async.wait_group %0;" :: "n"(STAGES - 2) : "memory");
        __syncthreads();
        const uint32_t* As = sA + (c % STAGES) * A_WORDS;
        const uint32_t* Bs = sB + (c % STAGES) * B_WORDS;

        #pragma unroll
        for (int ks = 0; ks < 2; ks++) {
            const int kk = ks * 8;
            uint32_t af[4][4];
            #pragma unroll
            for (int mt = 0; mt < 4; mt++) {
                int r = m0w + mt * 16;
                af[mt][0] = As[(r + g    ) * AST + kk + t    ];
                af[mt][1] = As[(r + g + 8) * AST + kk + t    ];
                af[mt][2] = As[(r + g    ) * AST + kk + t + 4];
                af[mt][3] = As[(r + g + 8) * AST + kk + t + 4];
            }
            uint32_t bf[5][2];
            #pragma unroll
            for (int nt = 0; nt < 5; nt++) {
                int nc = n0w + nt * 8 + g;
                bf[nt][0] = Bs[(kk + t    ) * BST + nc];
                bf[nt][1] = Bs[(kk + t + 4) * BST + nc];
            }
            #pragma unroll
            for (int mt = 0; mt < 4; mt++)
                #pragma unroll
                for (int nt = 0; nt < 5; nt++)
                    mma_tf32(acc[mt][nt], af[mt], bf[nt]);
        }
        if (FUSED && c + 1 < nCh) loadA_fused(c + 1);  // overlap with tensor drain
        int nx = c + STAGES - 1;
        if (nx < nCh) issue(nx);
        asm volatile("cp.async.commit_group;" ::: "memory");
    }

    // epilogue (float2 stores; col pairs never straddle the N=300 edge)
    #pragma unroll
    for (int mt = 0; mt < 4; mt++) {
        #pragma unroll
        for (int half = 0; half < 2; half++) {
            int row = rowBase + m0w + mt * 16 + g + half * 8;
            if (row >= M) continue;
            #pragma unroll
            for (int nt = 0; nt < 5; nt++) {
                int col = colBase + n0w + nt * 8 + t * 2;
                if (col >= HIDDEN) continue;
                float vx = acc[mt][nt][half * 2 + 0];
                float vy = acc[mt][nt][half * 2 + 1];
                if (bias)   { vx += bias[col]; vy += bias[col + 1]; }
                if (addsrc) {
                    float2 a = *reinterpret_cast<const float2*>(addsrc + (size_t)row * HIDDEN + col);
                    vx += a.x; vy += a.y;
                }
                if (rawout) {
                    float2 r; r.x = vx; r.y = vy;
                    *reinterpret_cast<float2*>(rawout + (size_t)row * HIDDEN + col) = r;
                }
                if (doRelu) { vx = fmaxf(vx, 0.f); vy = fmaxf(vy, 0.f); }
                float2 o; o.x = vx; o.y = vy;
                *reinterpret_cast<float2*>(C + (size_t)row * HIDDEN + col) = o;
            }
        }
    }
}

// ---------------- atom aggregation (float4) ----------------
__global__ __launch_bounds__(320) void gather_atoms4(
    const float4* __restrict__ msg4, const float* __restrict__ w_bonds,
    const int* __restrict__ a2b, float4* __restrict__ out4, int outStride4, int doRound)
{
    const int tx = threadIdx.x;
    const int ty = threadIdx.y;
    const int a  = blockIdx.x * 4 + ty;
    __shared__ int   sb[4][MAX_NB];
    __shared__ float sw[4][MAX_NB];
    if (a < N_ATOMS && tx < MAX_NB) {
        int b = a2b[(size_t)a * MAX_NB + tx];
        sb[ty][tx] = b;
        sw[ty][tx] = w_bonds[b];
    }
    __syncthreads();
    if (a < N_ATOMS && tx < H4) {
        float4 acc = make_float4(0.f, 0.f, 0.f, 0.f);
        #pragma unroll
        for (int k = 0; k < MAX_NB; k++) {
            float  w = sw[ty][k];
            float4 v = msg4[(size_t)sb[ty][k] * H4 + tx];
            acc.x = fmaf(w, v.x, acc.x);
            acc.y = fmaf(w, v.y, acc.y);
            acc.z = fmaf(w, v.z, acc.z);
            acc.w = fmaf(w, v.w, acc.w);
        }
        if (doRound) {
            acc.x = f2tf_f(acc.x); acc.y = f2tf_f(acc.y);
            acc.z = f2tf_f(acc.z); acc.w = f2tf_f(acc.w);
        }
        out4[(size_t)a * outStride4 + tx] = acc;
    }
}

// ---------------- readout (float4) ----------------
__global__ __launch_bounds__(320) void readout4(
    const float4* __restrict__ ah4, const float* __restrict__ w_atoms,
    const float* __restrict__ dop, float4* __restrict__ out4)
{
    const int tx = threadIdx.x;
    const int ty = threadIdx.y;
    const int m  = blockIdx.x * 4 + ty;
    if (m >= N_MOLS || tx >= H4) return;
    const int base = 1 + m * ATOMS_PER_MOL;
    float4 s = make_float4(0.f, 0.f, 0.f, 0.f);
    float ws = 0.f;
    #pragma unroll 5
    for (int i = 0; i < ATOMS_PER_MOL; i++) {
        float  w = w_atoms[base + i];
        float4 v = ah4[(size_t)(base + i) * H4 + tx];
        ws += w;
        s.x = fmaf(w, v.x, s.x);
        s.y = fmaf(w, v.y, s.y);
        s.z = fmaf(w, v.z, s.z);
        s.w = fmaf(w, v.w, s.w);
    }
    float sc = dop[m] / ws;
    s.x *= sc; s.y *= sc; s.z *= sc; s.w *= sc;
    out4[(size_t)m * H4 + tx] = s;
}

// ---------------- launch ----------------
extern "C" void kernel_launch(void* const* d_in, const int* in_sizes, int n_in,
                              void* d_out, int out_size)
{
    const float* f_atoms = (const float*)d_in[0];
    const float* f_bonds = (const float*)d_in[1];
    const float* w_atoms = (const float*)d_in[2];
    const float* w_bonds = (const float*)d_in[3];
    const float* dop     = (const float*)d_in[4];
    const float* W_i     = (const float*)d_in[5];
    const float* W_h     = (const float*)d_in[6];
    const float* W_o     = (const float*)d_in[7];
    const float* b_o     = (const float*)d_in[8];
    const int*   a2b     = (const int*)d_in[9];
    const int*   b2a     = (const int*)d_in[10];
    const int*   b2revb  = (const int*)d_in[11];
    float* out = (float*)d_out;

    float *inp, *msgA, *msgB, *amsg, *ah, *fbt, *cat, *Wi, *Wh, *WoC;
    cudaGetSymbolAddress((void**)&inp,  g_inp);
    cudaGetSymbolAddress((void**)&msgA, g_msgA);
    cudaGetSymbolAddress((void**)&msgB, g_msgB);
    cudaGetSymbolAddress((void**)&amsg, g_amsg);
    cudaGetSymbolAddress((void**)&ah,   g_ah);
    cudaGetSymbolAddress((void**)&fbt,  g_fbt);
    cudaGetSymbolAddress((void**)&cat,  g_cat);
    cudaGetSymbolAddress((void**)&Wi,   g_Wi);
    cudaGetSymbolAddress((void**)&Wh,   g_Wh);
    cudaGetSymbolAddress((void**)&WoC,  g_WoC);

    cudaFuncSetAttribute(tgemm300<0>, cudaFuncAttributeMaxDynamicSharedMemorySize, SMEM_BYTES);
    cudaFuncSetAttribute(tgemm300<1>, cudaFuncAttributeMaxDynamicSharedMemorySize, SMEM_BYTES);

    dim3 blk(256);
    dim3 gridBonds((HIDDEN + TBN - 1) / TBN, (N_BONDS + TBM - 1) / TBM);   // (2, 1563)
    dim3 gridAtoms((HIDDEN + TBN - 1) / TBN, (N_ATOMS + TBM - 1) / TBM);   // (2, 782)
    dim3 vblk(80, 4);

    // pre-round / reshape everything the GEMMs consume
    {
        int n;
        n = N_BONDS * FB_PAD;
        cvt_pad      <<<(n + 255) / 256, 256>>>(f_bonds, fbt, n, BOND_FDIM, FB_PAD);
        n = N_ATOMS * 136;
        cvt_cat_atoms<<<(n + 255) / 256, 256>>>(f_atoms, cat, n);
        n = BOND_FDIM * HIDDEN;
        cvt_flat     <<<(n + 255) / 256, 256>>>(W_i, Wi, n);
        n = HIDDEN * HIDDEN;
        cvt_flat     <<<(n + 255) / 256, 256>>>(W_h, Wh, n);
        n = CAT_K * HIDDEN;
        cvt_wo_cat   <<<(n + 255) / 256, 256>>>(W_o, WoC, n);
    }

    // inp = f_bonds @ W_i ; msgA = relu(inp)
    tgemm300<0><<<gridBonds, blk, SMEM_BYTES>>>(fbt, FB_PAD, Wi, msgA,
                                                nullptr, nullptr, inp, N_BONDS, BOND_FDIM, 1,
                                                nullptr, nullptr, nullptr, nullptr, nullptr);

    float* cur = msgA;
    float* nxt = msgB;
    for (int d = 0; d < DEPTH - 1; ++d) {
        gather_atoms4<<<(N_ATOMS + 3) / 4, vblk>>>(
            (const float4*)cur, w_bonds, a2b, (float4*)amsg, H4, 0);
        // nxt = relu(inp + (amsg[b2a] - w*cur[b2revb]) @ W_h)   -- bond_update fused
        tgemm300<1><<<gridBonds, blk, SMEM_BYTES>>>(nullptr, HIDDEN, Wh, nxt,
                                                    inp, nullptr, nullptr, N_BONDS, HIDDEN, 1,
                                                    amsg, cur, b2a, b2revb, w_bonds);
        float* sw = cur; cur = nxt; nxt = sw;
    }

    // final gather writes amsg (tf32-rounded) straight into cat cols [0,300)
    gather_atoms4<<<(N_ATOMS + 3) / 4, vblk>>>(
        (const float4*)cur, w_bonds, a2b, (float4*)cat, CAT4, 1);

    // ah = relu([amsg | f_atoms] @ WoC + b_o)   -- single fused K=436 GEMM
    tgemm300<0><<<gridAtoms, blk, SMEM_BYTES>>>(cat, CAT_K, WoC, ah,
                                                nullptr, b_o, nullptr, N_ATOMS, CAT_K, 1,
                                                nullptr, nullptr, nullptr, nullptr, nullptr);

    readout4<<<(N_MOLS + 3) / 4, vblk>>>(
        (const float4*)ah, w_atoms, dop, (float4*)out);
}

// round 12
// speedup vs baseline: 1.1210x; 1.1210x over previous
#include <cuda_runtime.h>
#include <cuda_fp16.h>
#include <cstdint>

#define N_MOLS        2000
#define ATOMS_PER_MOL 50
#define N_ATOMS       (N_MOLS * ATOMS_PER_MOL + 1)   // 100001
#define N_BONDS       200001
#define MAX_NB        6
#define ATOM_FDIM     133
#define BOND_FDIM     147
#define HIDDEN        300
#define DEPTH         4
#define H4            (HIDDEN / 4)
#define FBH           152                    // f_bonds halves padded (16B rows: 304B)
#define WH_PAD        304                    // W_h K padded halves (608B rows)
#define CATH          440                    // cat K padded halves (880B rows)

// ---------------- persistent scratch ----------------
__device__ __align__(16) float  g_inp [(size_t)N_BONDS * HIDDEN];
__device__ __align__(16) float  g_msg [(size_t)N_BONDS * HIDDEN];
__device__ __align__(16) float  g_amsg[(size_t)N_ATOMS * HIDDEN];
__device__ __align__(16) float  g_ah  [(size_t)N_ATOMS * HIDDEN];
__device__ __align__(16) __half g_tmpH[(size_t)N_BONDS * WH_PAD];   // fp16 bond message (GEMM A)
__device__ __align__(16) __half g_fbtH[(size_t)N_BONDS * FBH];      // fp16 f_bonds, padded
__device__ __align__(16) __half g_catH[(size_t)N_ATOMS * CATH];     // fp16 [amsg | f_atoms | 0]
__device__ __align__(16) __half g_WiT [HIDDEN * 160];               // W_i^T  [300][160]
__device__ __align__(16) __half g_WhT [HIDDEN * WH_PAD];            // W_h^T  [300][304]
__device__ __align__(16) __half g_WoT [HIDDEN * CATH];              // WoC^T  [300][440]

// ---------------- pre-conversion kernels ----------------
__global__ void cvt_padH(const float* __restrict__ in, __half* __restrict__ out,
                         int n, int cin, int coutH) {
    int i = blockIdx.x * blockDim.x + threadIdx.x;
    if (i >= n) return;
    int r = i / coutH, c = i - r * coutH;
    out[i] = (c < cin) ? __float2half_rn(in[(size_t)r * cin + c]) : __half(0.f);
}
// transpose weight [K,300] -> [300][kpad] half (n-major, k-contiguous), zero pad
__global__ void cvt_wtrH(const float* __restrict__ W, __half* __restrict__ Bt,
                         int K, int kpad, int n) {   // n = 300*kpad
    int i = blockIdx.x * blockDim.x + threadIdx.x;
    if (i >= n) return;
    int nn = i / kpad, k = i - nn * kpad;
    Bt[i] = (k < K) ? __float2half_rn(W[(size_t)k * HIDDEN + nn]) : __half(0.f);
}
// WoC^T: Bt[n][kp], kp<300 -> Wo[133+kp][n], kp<433 -> Wo[kp-300][n], else 0
__global__ void cvt_wo_trH(const float* __restrict__ Wo, __half* __restrict__ Bt, int n) {
    int i = blockIdx.x * blockDim.x + threadIdx.x;   // n = 300*CATH
    if (i >= n) return;
    int nn = i / CATH, kp = i - nn * CATH;
    float v = 0.f;
    if (kp < HIDDEN)                  v = Wo[(size_t)(ATOM_FDIM + kp) * HIDDEN + nn];
    else if (kp < HIDDEN + ATOM_FDIM) v = Wo[(size_t)(kp - HIDDEN) * HIDDEN + nn];
    Bt[i] = __float2half_rn(v);
}
// cat cols [300, 440): fp16 f_atoms then zero pad
__global__ void cvt_cat_atomsH(const float* __restrict__ fa, __half* __restrict__ cat, int n) {
    int i = blockIdx.x * blockDim.x + threadIdx.x;   // n = N_ATOMS * 140
    if (i >= n) return;
    int r = i / 140, c = i - r * 140;
    cat[(size_t)r * CATH + HIDDEN + c] =
        (c < ATOM_FDIM) ? __float2half_rn(fa[(size_t)r * ATOM_FDIM + c]) : __half(0.f);
}

// ---------------- fp16 mma ----------------
__device__ __forceinline__ void mma_f16(float* c, const uint32_t* a, const uint32_t* b) {
    asm volatile(
        "mma.sync.aligned.m16n8k16.row.col.f32.f16.f16.f32 "
        "{%0,%1,%2,%3}, {%4,%5,%6,%7}, {%8,%9}, {%0,%1,%2,%3};"
        : "+f"(c[0]), "+f"(c[1]), "+f"(c[2]), "+f"(c[3])
        : "r"(a[0]), "r"(a[1]), "r"(a[2]), "r"(a[3]), "r"(b[0]), "r"(b[1]));
}

// ---------------- pipelined fp16 tensor-core GEMM, 64x40 warp tiles, TBK=32 ----------------
// C[M,300] = relu?( A[M,K] @ Bt^T (+ addsrc) (+ bias) )
// A: [M][ldaH] half row-major. Bt: [300][ldbH] half n-major (k contiguous).
// smem word = 2 halves (one k-pair). Strides 20 words/row -> conflict-free (R8-proven pattern).
#define TBM 128
#define TBN 160
#define STAGES 4
#define RST 20                         // words per (row|n) per chunk: 16 data + 4 pad
#define A_WORDS (TBM * RST)            // 2560
#define B_WORDS (TBN * RST)            // 3200
#define SMEM_BYTES (STAGES * (A_WORDS + B_WORDS) * 4)   // 92160

__global__ __launch_bounds__(256, 2) void hgemm300(
    const __half* __restrict__ A, int ldaH,
    const __half* __restrict__ Bt, int ldbH,
    float* __restrict__ C,
    const float* __restrict__ addsrc,
    const float* __restrict__ bias,
    float* __restrict__ rawout,
    int M, int nCh, int doRelu)
{
    extern __shared__ uint32_t sm[];
    uint32_t* sA = sm;
    uint32_t* sB = sm + STAGES * A_WORDS;
    const uint32_t sAaddr = (uint32_t)__cvta_generic_to_shared(sA);
    const uint32_t sBaddr = (uint32_t)__cvta_generic_to_shared(sB);

    const int tid  = threadIdx.x;
    const int lane = tid & 31;
    const int warp = tid >> 5;          // 0..7
    const int g = lane >> 2;
    const int t = lane & 3;
    const int m0w = (warp & 1) * 64;    // 2 warps along M
    const int n0w = (warp >> 1) * 40;   // 4 warps along N

    const int rowBase = blockIdx.y * TBM;
    const int colBase = blockIdx.x * TBN;

    auto issue = [&](int c) {
        const int stg = c % STAGES;
        // A: 128 rows x 32 halves = 512 x 16B chunks
        #pragma unroll
        for (int it = 0; it < 2; it++) {
            int e   = it * 256 + tid;
            int row = e >> 2;
            int k16 = e & 3;                      // which 16B (8 halves) within chunk
            int gr  = rowBase + row;
            int k0h = c * 32 + k16 * 8;
            int by  = (gr < M && k0h < ldaH) ? 16 : 0;
            const __half* src = by ? (A + (size_t)gr * ldaH + k0h) : A;
            uint32_t dst = sAaddr + (uint32_t)(stg * A_WORDS + row * RST + k16 * 4) * 4u;
            asm volatile("cp.async.ca.shared.global [%0], [%1], 16, %2;"
                         :: "r"(dst), "l"(src), "r"(by) : "memory");
        }
        // B: 160 n-rows x 32 halves = 640 x 16B chunks
        #pragma unroll
        for (int it = 0; it < 3; it++) {
            int e = it * 256 + tid;
            if (it == 2 && tid >= 128) break;
            int n   = e >> 2;
            int k16 = e & 3;
            int gn  = colBase + n;
            int k0h = c * 32 + k16 * 8;
            int by  = (gn < HIDDEN && k0h < ldbH) ? 16 : 0;
            const __half* src = by ? (Bt + (size_t)gn * ldbH + k0h) : Bt;
            uint32_t dst = sBaddr + (uint32_t)(stg * B_WORDS + n * RST + k16 * 4) * 4u;
            asm volatile("cp.async.ca.shared.global [%0], [%1], 16, %2;"
                         :: "r"(dst), "l"(src), "r"(by) : "memory");
        }
    };

    float acc[4][5][4];
    #pragma unroll
    for (int i = 0; i < 4; i++)
        #pragma unroll
        for (int j = 0; j < 5; j++)
            #pragma unroll
            for (int q = 0; q < 4; q++) acc[i][j][q] = 0.f;

    #pragma unroll
    for (int s = 0; s < STAGES - 1; s++) {
        if (s < nCh) issue(s);
        asm volatile("cp.async.commit_group;" ::: "memory");
    }

    for (int c = 0; c < nCh; c++) {
        asm volatile("cp.async.wait_group %0;" :: "n"(STAGES - 2) : "memory");
        __syncthreads();
        const uint32_t* As = sA + (c % STAGES) * A_WORDS;
        const uint32_t* Bs = sB + (c % STAGES) * B_WORDS;

        #pragma unroll
        for (int ks = 0; ks < 2; ks++) {         // two k16-steps per 32-half chunk
            const int kkw = ks * 8;              // word offset (8 pairs = 16 halves)
            uint32_t af[4][4];
            #pragma unroll
            for (int mt = 0; mt < 4; mt++) {
                int r = m0w + mt * 16;
                af[mt][0] = As[(r + g    ) * RST + kkw + t    ];
                af[mt][1] = As[(r + g + 8) * RST + kkw + t    ];
                af[mt][2] = As[(r + g    ) * RST + kkw + t + 4];
                af[mt][3] = As[(r + g + 8) * RST + kkw + t + 4];
            }
            uint32_t bf[5][2];
            #pragma unroll
            for (int nt = 0; nt < 5; nt++) {
                int nc = n0w + nt * 8 + g;
                bf[nt][0] = Bs[nc * RST + kkw + t    ];
                bf[nt][1] = Bs[nc * RST + kkw + t + 4];
            }
            #pragma unroll
            for (int mt = 0; mt < 4; mt++)
                #pragma unroll
                for (int nt = 0; nt < 5; nt++)
                    mma_f16(acc[mt][nt], af[mt], bf[nt]);
        }
        int nx = c + STAGES - 1;
        if (nx < nCh) issue(nx);
        asm volatile("cp.async.commit_group;" ::: "memory");
    }

    // epilogue (float2 stores; col pairs never straddle the N=300 edge)
    #pragma unroll
    for (int mt = 0; mt < 4; mt++) {
        #pragma unroll
        for (int half = 0; half < 2; half++) {
            int row = rowBase + m0w + mt * 16 + g + half * 8;
            if (row >= M) continue;
            #pragma unroll
            for (int nt = 0; nt < 5; nt++) {
                int col = colBase + n0w + nt * 8 + t * 2;
                if (col >= HIDDEN) continue;
                float vx = acc[mt][nt][half * 2 + 0];
                float vy = acc[mt][nt][half * 2 + 1];
                if (bias)   { vx += bias[col]; vy += bias[col + 1]; }
                if (addsrc) {
                    float2 a = *reinterpret_cast<const float2*>(addsrc + (size_t)row * HIDDEN + col);
                    vx += a.x; vy += a.y;
                }
                if (rawout) {
                    float2 r; r.x = vx; r.y = vy;
                    *reinterpret_cast<float2*>(rawout + (size_t)row * HIDDEN + col) = r;
                }
                if (doRelu) { vx = fmaxf(vx, 0.f); vy = fmaxf(vy, 0.f); }
                float2 o; o.x = vx; o.y = vy;
                *reinterpret_cast<float2*>(C + (size_t)row * HIDDEN + col) = o;
            }
        }
    }
}

// ---------------- atom aggregation (float4); optional fp16 output into cat ----------------
__global__ __launch_bounds__(320) void gather_atoms4(
    const float4* __restrict__ msg4, const float* __restrict__ w_bonds,
    const int* __restrict__ a2b, float4* __restrict__ outF, __half* __restrict__ outH)
{
    const int tx = threadIdx.x;        // 0..79
    const int ty = threadIdx.y;        // 0..3
    const int a  = blockIdx.x * 4 + ty;
    __shared__ int   sb[4][MAX_NB];
    __shared__ float sw[4][MAX_NB];
    if (a < N_ATOMS && tx < MAX_NB) {
        int b = a2b[(size_t)a * MAX_NB + tx];
        sb[ty][tx] = b;
        sw[ty][tx] = w_bonds[b];
    }
    __syncthreads();
    if (a < N_ATOMS && tx < H4) {
        float4 acc = make_float4(0.f, 0.f, 0.f, 0.f);
        #pragma unroll
        for (int k = 0; k < MAX_NB; k++) {
            float  w = sw[ty][k];
            float4 v = msg4[(size_t)sb[ty][k] * H4 + tx];
            acc.x = fmaf(w, v.x, acc.x);
            acc.y = fmaf(w, v.y, acc.y);
            acc.z = fmaf(w, v.z, acc.z);
            acc.w = fmaf(w, v.w, acc.w);
        }
        if (outF) {
            outF[(size_t)a * H4 + tx] = acc;
        } else {
            __half2* p = reinterpret_cast<__half2*>(outH + (size_t)a * CATH + tx * 4);
            p[0] = __floats2half2_rn(acc.x, acc.y);
            p[1] = __floats2half2_rn(acc.z, acc.w);
        }
    }
}

// ---------------- bond update -> fp16 GEMM A operand (pads zeroed) ----------------
__global__ __launch_bounds__(320) void bond_update4H(
    const float4* __restrict__ amsg4, const float4* __restrict__ msg4,
    const float* __restrict__ w_bonds,
    const int* __restrict__ b2a, const int* __restrict__ b2revb,
    __half* __restrict__ tmpH)
{
    const int tx = threadIdx.x;
    const int ty = threadIdx.y;
    const int b  = blockIdx.x * 4 + ty;
    __shared__ int   sa[4], srb[4];
    __shared__ float sw[4];
    if (b < N_BONDS && tx == 0) { sa[ty] = b2a[b]; srb[ty] = b2revb[b]; sw[ty] = w_bonds[b]; }
    __syncthreads();
    if (b >= N_BONDS) return;
    if (tx < H4) {
        float4 am = amsg4[(size_t)sa[ty]  * H4 + tx];
        float4 mv = msg4 [(size_t)srb[ty] * H4 + tx];
        float  w  = sw[ty];
        __half2* p = reinterpret_cast<__half2*>(tmpH + (size_t)b * WH_PAD + tx * 4);
        p[0] = __floats2half2_rn(am.x - w * mv.x, am.y - w * mv.y);
        p[1] = __floats2half2_rn(am.z - w * mv.z, am.w - w * mv.w);
    } else if (tx == H4) {   // zero halves 300..303 (keep GEMM pads finite)
        *reinterpret_cast<uint2*>(tmpH + (size_t)b * WH_PAD + HIDDEN) = make_uint2(0u, 0u);
    }
}

// ---------------- readout (float4) ----------------
__global__ __launch_bounds__(320) void readout4(
    const float4* __restrict__ ah4, const float* __restrict__ w_atoms,
    const float* __restrict__ dop, float4* __restrict__ out4)
{
    const int tx = threadIdx.x;
    const int ty = threadIdx.y;
    const int m  = blockIdx.x * 4 + ty;
    if (m >= N_MOLS || tx >= H4) return;
    const int base = 1 + m * ATOMS_PER_MOL;
    float4 s = make_float4(0.f, 0.f, 0.f, 0.f);
    float ws = 0.f;
    #pragma unroll 5
    for (int i = 0; i < ATOMS_PER_MOL; i++) {
        float  w = w_atoms[base + i];
        float4 v = ah4[(size_t)(base + i) * H4 + tx];
        ws += w;
        s.x = fmaf(w, v.x, s.x);
        s.y = fmaf(w, v.y, s.y);
        s.z = fmaf(w, v.z, s.z);
        s.w = fmaf(w, v.w, s.w);
    }
    float sc = dop[m] / ws;
    s.x *= sc; s.y *= sc; s.z *= sc; s.w *= sc;
    out4[(size_t)m * H4 + tx] = s;
}

// ---------------- launch ----------------
extern "C" void kernel_launch(void* const* d_in, const int* in_sizes, int n_in,
                              void* d_out, int out_size)
{
    const float* f_atoms = (const float*)d_in[0];
    const float* f_bonds = (const float*)d_in[1];
    const float* w_atoms = (const float*)d_in[2];
    const float* w_bonds = (const float*)d_in[3];
    const float* dop     = (const float*)d_in[4];
    const float* W_i     = (const float*)d_in[5];
    const float* W_h     = (const float*)d_in[6];
    const float* W_o     = (const float*)d_in[7];
    const float* b_o     = (const float*)d_in[8];
    const int*   a2b     = (const int*)d_in[9];
    const int*   b2a     = (const int*)d_in[10];
    const int*   b2revb  = (const int*)d_in[11];
    float* out = (float*)d_out;

    float *inp, *msg, *amsg, *ah;
    __half *tmpH, *fbtH, *catH, *WiT, *WhT, *WoT;
    cudaGetSymbolAddress((void**)&inp,  g_inp);
    cudaGetSymbolAddress((void**)&msg,  g_msg);
    cudaGetSymbolAddress((void**)&amsg, g_amsg);
    cudaGetSymbolAddress((void**)&ah,   g_ah);
    cudaGetSymbolAddress((void**)&tmpH, g_tmpH);
    cudaGetSymbolAddress((void**)&fbtH, g_fbtH);
    cudaGetSymbolAddress((void**)&catH, g_catH);
    cudaGetSymbolAddress((void**)&WiT,  g_WiT);
    cudaGetSymbolAddress((void**)&WhT,  g_WhT);
    cudaGetSymbolAddress((void**)&WoT,  g_WoT);

    cudaFuncSetAttribute(hgemm300, cudaFuncAttributeMaxDynamicSharedMemorySize, SMEM_BYTES);

    dim3 blk(256);
    dim3 gridBonds(2, (N_BONDS + TBM - 1) / TBM);   // (2, 1563)
    dim3 gridAtoms(2, (N_ATOMS + TBM - 1) / TBM);   // (2, 782)
    dim3 vblk(80, 4);

    // pre-round / transpose everything the GEMMs consume
    {
        int n;
        n = N_BONDS * FBH;
        cvt_padH      <<<(n + 255) / 256, 256>>>(f_bonds, fbtH, n, BOND_FDIM, FBH);
        n = N_ATOMS * 140;
        cvt_cat_atomsH<<<(n + 255) / 256, 256>>>(f_atoms, catH, n);
        n = HIDDEN * 160;
        cvt_wtrH      <<<(n + 255) / 256, 256>>>(W_i, WiT, BOND_FDIM, 160, n);
        n = HIDDEN * WH_PAD;
        cvt_wtrH      <<<(n + 255) / 256, 256>>>(W_h, WhT, HIDDEN, WH_PAD, n);
        n = HIDDEN * CATH;
        cvt_wo_trH    <<<(n + 255) / 256, 256>>>(W_o, WoT, n);
    }

    // inp = f_bonds @ W_i ; msg = relu(inp)        nCh = ceil(152/32) = 5
    hgemm300<<<gridBonds, blk, SMEM_BYTES>>>(fbtH, FBH, WiT, 160, msg,
                                             nullptr, nullptr, inp, N_BONDS, 5, 1);

    for (int d = 0; d < DEPTH - 1; ++d) {
        gather_atoms4<<<(N_ATOMS + 3) / 4, vblk>>>(
            (const float4*)msg, w_bonds, a2b, (float4*)amsg, nullptr);
        bond_update4H<<<(N_BONDS + 3) / 4, vblk>>>(
            (const float4*)amsg, (const float4*)msg, w_bonds, b2a, b2revb, tmpH);
        // msg = relu(inp + tmp @ W_h)              nCh = ceil(304/32) = 10
        hgemm300<<<gridBonds, blk, SMEM_BYTES>>>(tmpH, WH_PAD, WhT, WH_PAD, msg,
                                                 inp, nullptr, nullptr, N_BONDS, 10, 1);
    }

    // final gather writes fp16 amsg straight into cat cols [0,300)
    gather_atoms4<<<(N_ATOMS + 3) / 4, vblk>>>(
        (const float4*)msg, w_bonds, a2b, nullptr, catH);

    // ah = relu([amsg | f_atoms] @ WoC + b_o)      nCh = ceil(440/32) = 14
    hgemm300<<<gridAtoms, blk, SMEM_BYTES>>>(catH, CATH, WoT, CATH, ah,
                                             nullptr, b_o, nullptr, N_ATOMS, 14, 1);

    readout4<<<(N_MOLS + 3) / 4, vblk>>>(
        (const float4*)ah, w_atoms, dop, (float4*)out);
}

// round 13
// speedup vs baseline: 1.6471x; 1.4693x over previous
#include <cuda_runtime.h>
#include <cuda_fp16.h>
#include <cstdint>

#define N_MOLS        2000
#define ATOMS_PER_MOL 50
#define N_ATOMS       (N_MOLS * ATOMS_PER_MOL + 1)   // 100001
#define N_BONDS       200001
#define MAX_NB        6
#define ATOM_FDIM     133
#define BOND_FDIM     147
#define HIDDEN        300
#define DEPTH         4
#define H4            (HIDDEN / 4)
#define FBH           152                    // f_bonds halves padded (304B rows)
#define MSGH          304                    // msg/amsg/tmp row stride in halves (608B)
#define CATH          440                    // cat K padded halves (880B rows)

// ---------------- persistent scratch ----------------
__device__ __align__(16) float  g_inp  [(size_t)N_BONDS * HIDDEN];  // fp32 (precision anchor)
__device__ __align__(16) float  g_ah   [(size_t)N_ATOMS * HIDDEN];  // fp32
__device__ __align__(16) __half g_msgH [(size_t)N_BONDS * MSGH];    // fp16 message
__device__ __align__(16) __half g_amsgH[(size_t)N_ATOMS * MSGH];    // fp16 atom aggregate
__device__ __align__(16) __half g_tmpH [(size_t)N_BONDS * MSGH];    // fp16 bond message (GEMM A)
__device__ __align__(16) __half g_fbtH [(size_t)N_BONDS * FBH];     // fp16 f_bonds, padded
__device__ __align__(16) __half g_catH [(size_t)N_ATOMS * CATH];    // fp16 [amsg | f_atoms | 0]
__device__ __align__(16) __half g_WiT  [HIDDEN * 160];              // W_i^T  [300][160]
__device__ __align__(16) __half g_WhT  [HIDDEN * MSGH];             // W_h^T  [300][304]
__device__ __align__(16) __half g_WoT  [HIDDEN * CATH];             // WoC^T  [300][440]

// ---------------- pre-conversion kernels ----------------
__global__ void cvt_padH(const float* __restrict__ in, __half* __restrict__ out,
                         int n, int cin, int coutH) {
    int i = blockIdx.x * blockDim.x + threadIdx.x;
    if (i >= n) return;
    int r = i / coutH, c = i - r * coutH;
    out[i] = (c < cin) ? __float2half_rn(in[(size_t)r * cin + c]) : __half(0.f);
}
__global__ void cvt_wtrH(const float* __restrict__ W, __half* __restrict__ Bt,
                         int K, int kpad, int n) {   // n = 300*kpad
    int i = blockIdx.x * blockDim.x + threadIdx.x;
    if (i >= n) return;
    int nn = i / kpad, k = i - nn * kpad;
    Bt[i] = (k < K) ? __float2half_rn(W[(size_t)k * HIDDEN + nn]) : __half(0.f);
}
__global__ void cvt_wo_trH(const float* __restrict__ Wo, __half* __restrict__ Bt, int n) {
    int i = blockIdx.x * blockDim.x + threadIdx.x;   // n = 300*CATH
    if (i >= n) return;
    int nn = i / CATH, kp = i - nn * CATH;
    float v = 0.f;
    if (kp < HIDDEN)                  v = Wo[(size_t)(ATOM_FDIM + kp) * HIDDEN + nn];
    else if (kp < HIDDEN + ATOM_FDIM) v = Wo[(size_t)(kp - HIDDEN) * HIDDEN + nn];
    Bt[i] = __float2half_rn(v);
}
__global__ void cvt_cat_atomsH(const float* __restrict__ fa, __half* __restrict__ cat, int n) {
    int i = blockIdx.x * blockDim.x + threadIdx.x;   // n = N_ATOMS * 140
    if (i >= n) return;
    int r = i / 140, c = i - r * 140;
    cat[(size_t)r * CATH + HIDDEN + c] =
        (c < ATOM_FDIM) ? __float2half_rn(fa[(size_t)r * ATOM_FDIM + c]) : __half(0.f);
}

// ---------------- fp16 mma ----------------
__device__ __forceinline__ void mma_f16(float* c, const uint32_t* a, const uint32_t* b) {
    asm volatile(
        "mma.sync.aligned.m16n8k16.row.col.f32.f16.f16.f32 "
        "{%0,%1,%2,%3}, {%4,%5,%6,%7}, {%8,%9}, {%0,%1,%2,%3};"
        : "+f"(c[0]), "+f"(c[1]), "+f"(c[2]), "+f"(c[3])
        : "r"(a[0]), "r"(a[1]), "r"(a[2]), "r"(a[3]), "r"(b[0]), "r"(b[1]));
}

// ---------------- pipelined fp16 tensor-core GEMM, 64x40 warp tiles, TBK=32 ----------------
// Out = relu?( A[M,K] @ Bt^T (+ addsrc) (+ bias) )
// Exactly one of Ch (fp16, stride ldcH) / Cf (fp32, stride 300) is non-null.
// rawoutF optionally stores the pre-relu value in fp32 (stride 300).
#define TBM 128
#define TBN 160
#define STAGES 4
#define RST 20
#define A_WORDS (TBM * RST)            // 2560
#define B_WORDS (TBN * RST)            // 3200
#define SMEM_BYTES (STAGES * (A_WORDS + B_WORDS) * 4)   // 92160

__global__ __launch_bounds__(256, 2) void hgemm300(
    const __half* __restrict__ A, int ldaH,
    const __half* __restrict__ Bt, int ldbH,
    __half* __restrict__ Ch, int ldcH,
    float* __restrict__ Cf,
    const float* __restrict__ addsrc,
    const float* __restrict__ bias,
    float* __restrict__ rawoutF,
    int M, int nCh, int doRelu)
{
    extern __shared__ uint32_t sm[];
    uint32_t* sA = sm;
    uint32_t* sB = sm + STAGES * A_WORDS;
    const uint32_t sAaddr = (uint32_t)__cvta_generic_to_shared(sA);
    const uint32_t sBaddr = (uint32_t)__cvta_generic_to_shared(sB);

    const int tid  = threadIdx.x;
    const int lane = tid & 31;
    const int warp = tid >> 5;
    const int g = lane >> 2;
    const int t = lane & 3;
    const int m0w = (warp & 1) * 64;
    const int n0w = (warp >> 1) * 40;

    const int rowBase = blockIdx.y * TBM;
    const int colBase = blockIdx.x * TBN;

    auto issue = [&](int c) {
        const int stg = c % STAGES;
        #pragma unroll
        for (int it = 0; it < 2; it++) {
            int e   = it * 256 + tid;
            int row = e >> 2;
            int k16 = e & 3;
            int gr  = rowBase + row;
            int k0h = c * 32 + k16 * 8;
            int by  = (gr < M && k0h < ldaH) ? 16 : 0;
            const __half* src = by ? (A + (size_t)gr * ldaH + k0h) : A;
            uint32_t dst = sAaddr + (uint32_t)(stg * A_WORDS + row * RST + k16 * 4) * 4u;
            asm volatile("cp.async.ca.shared.global [%0], [%1], 16, %2;"
                         :: "r"(dst), "l"(src), "r"(by) : "memory");
        }
        #pragma unroll
        for (int it = 0; it < 3; it++) {
            int e = it * 256 + tid;
            if (it == 2 && tid >= 128) break;
            int n   = e >> 2;
            int k16 = e & 3;
            int gn  = colBase + n;
            int k0h = c * 32 + k16 * 8;
            int by  = (gn < HIDDEN && k0h < ldbH) ? 16 : 0;
            const __half* src = by ? (Bt + (size_t)gn * ldbH + k0h) : Bt;
            uint32_t dst = sBaddr + (uint32_t)(stg * B_WORDS + n * RST + k16 * 4) * 4u;
            asm volatile("cp.async.ca.shared.global [%0], [%1], 16, %2;"
                         :: "r"(dst), "l"(src), "r"(by) : "memory");
        }
    };

    float acc[4][5][4];
    #pragma unroll
    for (int i = 0; i < 4; i++)
        #pragma unroll
        for (int j = 0; j < 5; j++)
            #pragma unroll
            for (int q = 0; q < 4; q++) acc[i][j][q] = 0.f;

    #pragma unroll
    for (int s = 0; s < STAGES - 1; s++) {
        if (s < nCh) issue(s);
        asm volatile("cp.async.commit_group;" ::: "memory");
    }

    for (int c = 0; c < nCh; c++) {
        asm volatile("cp.async.wait_group %0;" :: "n"(STAGES - 2) : "memory");
        __syncthreads();
        const uint32_t* As = sA + (c % STAGES) * A_WORDS;
        const uint32_t* Bs = sB + (c % STAGES) * B_WORDS;

        #pragma unroll
        for (int ks = 0; ks < 2; ks++) {
            const int kkw = ks * 8;
            uint32_t af[4][4];
            #pragma unroll
            for (int mt = 0; mt < 4; mt++) {
                int r = m0w + mt * 16;
                af[mt][0] = As[(r + g    ) * RST + kkw + t    ];
                af[mt][1] = As[(r + g + 8) * RST + kkw + t    ];
                af[mt][2] = As[(r + g    ) * RST + kkw + t + 4];
                af[mt][3] = As[(r + g + 8) * RST + kkw + t + 4];
            }
            uint32_t bf[5][2];
            #pragma unroll
            for (int nt = 0; nt < 5; nt++) {
                int nc = n0w + nt * 8 + g;
                bf[nt][0] = Bs[nc * RST + kkw + t    ];
                bf[nt][1] = Bs[nc * RST + kkw + t + 4];
            }
            #pragma unroll
            for (int mt = 0; mt < 4; mt++)
                #pragma unroll
                for (int nt = 0; nt < 5; nt++)
                    mma_f16(acc[mt][nt], af[mt], bf[nt]);
        }
        int nx = c + STAGES - 1;
        if (nx < nCh) issue(nx);
        asm volatile("cp.async.commit_group;" ::: "memory");
    }

    // epilogue
    #pragma unroll
    for (int mt = 0; mt < 4; mt++) {
        #pragma unroll
        for (int half = 0; half < 2; half++) {
            int row = rowBase + m0w + mt * 16 + g + half * 8;
            if (row >= M) continue;
            #pragma unroll
            for (int nt = 0; nt < 5; nt++) {
                int col = colBase + n0w + nt * 8 + t * 2;
                if (col >= HIDDEN) continue;
                float vx = acc[mt][nt][half * 2 + 0];
                float vy = acc[mt][nt][half * 2 + 1];
                if (bias)   { vx += bias[col]; vy += bias[col + 1]; }
                if (addsrc) {
                    float2 a = *reinterpret_cast<const float2*>(addsrc + (size_t)row * HIDDEN + col);
                    vx += a.x; vy += a.y;
                }
                if (rawoutF) {
                    float2 r; r.x = vx; r.y = vy;
                    *reinterpret_cast<float2*>(rawoutF + (size_t)row * HIDDEN + col) = r;
                }
                if (doRelu) { vx = fmaxf(vx, 0.f); vy = fmaxf(vy, 0.f); }
                if (Ch) {
                    *reinterpret_cast<__half2*>(Ch + (size_t)row * ldcH + col) =
                        __floats2half2_rn(vx, vy);
                } else {
                    float2 o; o.x = vx; o.y = vy;
                    *reinterpret_cast<float2*>(Cf + (size_t)row * HIDDEN + col) = o;
                }
            }
        }
    }
}

// ---------------- atom aggregation: fp16 msg in -> fp16 out (amsg or cat) ----------------
__global__ __launch_bounds__(320) void gather_atomsH(
    const __half* __restrict__ msgH, const float* __restrict__ w_bonds,
    const int* __restrict__ a2b, __half* __restrict__ outH, int outStrideH)
{
    const int tx = threadIdx.x;        // 0..79
    const int ty = threadIdx.y;        // 0..3
    const int a  = blockIdx.x * 4 + ty;
    __shared__ int   sb[4][MAX_NB];
    __shared__ float sw[4][MAX_NB];
    if (a < N_ATOMS && tx < MAX_NB) {
        int b = a2b[(size_t)a * MAX_NB + tx];
        sb[ty][tx] = b;
        sw[ty][tx] = w_bonds[b];
    }
    __syncthreads();
    if (a < N_ATOMS && tx < H4) {
        float4 acc = make_float4(0.f, 0.f, 0.f, 0.f);
        #pragma unroll
        for (int k = 0; k < MAX_NB; k++) {
            float w = sw[ty][k];
            const __half2* p = reinterpret_cast<const __half2*>(
                msgH + (size_t)sb[ty][k] * MSGH + tx * 4);
            float2 v0 = __half22float2(p[0]);
            float2 v1 = __half22float2(p[1]);
            acc.x = fmaf(w, v0.x, acc.x);
            acc.y = fmaf(w, v0.y, acc.y);
            acc.z = fmaf(w, v1.x, acc.z);
            acc.w = fmaf(w, v1.y, acc.w);
        }
        __half2* o = reinterpret_cast<__half2*>(outH + (size_t)a * outStrideH + tx * 4);
        o[0] = __floats2half2_rn(acc.x, acc.y);
        o[1] = __floats2half2_rn(acc.z, acc.w);
    }
}

// ---------------- bond update: fp16 in -> fp16 GEMM A operand (pads zeroed) ----------------
__global__ __launch_bounds__(320) void bond_updateH(
    const __half* __restrict__ amsgH, const __half* __restrict__ msgH,
    const float* __restrict__ w_bonds,
    const int* __restrict__ b2a, const int* __restrict__ b2revb,
    __half* __restrict__ tmpH)
{
    const int tx = threadIdx.x;
    const int ty = threadIdx.y;
    const int b  = blockIdx.x * 4 + ty;
    __shared__ int   sa[4], srb[4];
    __shared__ float sw[4];
    if (b < N_BONDS && tx == 0) { sa[ty] = b2a[b]; srb[ty] = b2revb[b]; sw[ty] = w_bonds[b]; }
    __syncthreads();
    if (b >= N_BONDS) return;
    if (tx < H4) {
        const __half2* pa = reinterpret_cast<const __half2*>(amsgH + (size_t)sa[ty]  * MSGH + tx * 4);
        const __half2* pm = reinterpret_cast<const __half2*>(msgH  + (size_t)srb[ty] * MSGH + tx * 4);
        float2 a0 = __half22float2(pa[0]), a1 = __half22float2(pa[1]);
        float2 m0 = __half22float2(pm[0]), m1 = __half22float2(pm[1]);
        float w = sw[ty];
        __half2* o = reinterpret_cast<__half2*>(tmpH + (size_t)b * MSGH + tx * 4);
        o[0] = __floats2half2_rn(a0.x - w * m0.x, a0.y - w * m0.y);
        o[1] = __floats2half2_rn(a1.x - w * m1.x, a1.y - w * m1.y);
    } else if (tx == H4) {   // zero halves 300..303
        *reinterpret_cast<uint2*>(tmpH + (size_t)b * MSGH + HIDDEN) = make_uint2(0u, 0u);
    }
}

// ---------------- readout (float4, ah fp32) ----------------
__global__ __launch_bounds__(320) void readout4(
    const float4* __restrict__ ah4, const float* __restrict__ w_atoms,
    const float* __restrict__ dop, float4* __restrict__ out4)
{
    const int tx = threadIdx.x;
    const int ty = threadIdx.y;
    const int m  = blockIdx.x * 4 + ty;
    if (m >= N_MOLS || tx >= H4) return;
    const int base = 1 + m * ATOMS_PER_MOL;
    float4 s = make_float4(0.f, 0.f, 0.f, 0.f);
    float ws = 0.f;
    #pragma unroll 5
    for (int i = 0; i < ATOMS_PER_MOL; i++) {
        float  w = w_atoms[base + i];
        float4 v = ah4[(size_t)(base + i) * H4 + tx];
        ws += w;
        s.x = fmaf(w, v.x, s.x);
        s.y = fmaf(w, v.y, s.y);
        s.z = fmaf(w, v.z, s.z);
        s.w = fmaf(w, v.w, s.w);
    }
    float sc = dop[m] / ws;
    s.x *= sc; s.y *= sc; s.z *= sc; s.w *= sc;
    out4[(size_t)m * H4 + tx] = s;
}

// ---------------- launch ----------------
extern "C" void kernel_launch(void* const* d_in, const int* in_sizes, int n_in,
                              void* d_out, int out_size)
{
    const float* f_atoms = (const float*)d_in[0];
    const float* f_bonds = (const float*)d_in[1];
    const float* w_atoms = (const float*)d_in[2];
    const float* w_bonds = (const float*)d_in[3];
    const float* dop     = (const float*)d_in[4];
    const float* W_i     = (const float*)d_in[5];
    const float* W_h     = (const float*)d_in[6];
    const float* W_o     = (const float*)d_in[7];
    const float* b_o     = (const float*)d_in[8];
    const int*   a2b     = (const int*)d_in[9];
    const int*   b2a     = (const int*)d_in[10];
    const int*   b2revb  = (const int*)d_in[11];
    float* out = (float*)d_out;

    float *inp, *ah;
    __half *msgH, *amsgH, *tmpH, *fbtH, *catH, *WiT, *WhT, *WoT;
    cudaGetSymbolAddress((void**)&inp,   g_inp);
    cudaGetSymbolAddress((void**)&ah,    g_ah);
    cudaGetSymbolAddress((void**)&msgH,  g_msgH);
    cudaGetSymbolAddress((void**)&amsgH, g_amsgH);
    cudaGetSymbolAddress((void**)&tmpH,  g_tmpH);
    cudaGetSymbolAddress((void**)&fbtH,  g_fbtH);
    cudaGetSymbolAddress((void**)&catH,  g_catH);
    cudaGetSymbolAddress((void**)&WiT,   g_WiT);
    cudaGetSymbolAddress((void**)&WhT,   g_WhT);
    cudaGetSymbolAddress((void**)&WoT,   g_WoT);

    cudaFuncSetAttribute(hgemm300, cudaFuncAttributeMaxDynamicSharedMemorySize, SMEM_BYTES);

    dim3 blk(256);
    dim3 gridBonds(2, (N_BONDS + TBM - 1) / TBM);   // (2, 1563)
    dim3 gridAtoms(2, (N_ATOMS + TBM - 1) / TBM);   // (2, 782)
    dim3 vblk(80, 4);

    {
        int n;
        n = N_BONDS * FBH;
        cvt_padH      <<<(n + 255) / 256, 256>>>(f_bonds, fbtH, n, BOND_FDIM, FBH);
        n = N_ATOMS * 140;
        cvt_cat_atomsH<<<(n + 255) / 256, 256>>>(f_atoms, catH, n);
        n = HIDDEN * 160;
        cvt_wtrH      <<<(n + 255) / 256, 256>>>(W_i, WiT, BOND_FDIM, 160, n);
        n = HIDDEN * MSGH;
        cvt_wtrH      <<<(n + 255) / 256, 256>>>(W_h, WhT, HIDDEN, MSGH, n);
        n = HIDDEN * CATH;
        cvt_wo_trH    <<<(n + 255) / 256, 256>>>(W_o, WoT, n);
    }

    // inp(fp32) = f_bonds @ W_i ; msgH(fp16) = relu(inp)      nCh = 5
    hgemm300<<<gridBonds, blk, SMEM_BYTES>>>(fbtH, FBH, WiT, 160,
                                             msgH, MSGH, nullptr,
                                             nullptr, nullptr, inp, N_BONDS, 5, 1);

    for (int d = 0; d < DEPTH - 1; ++d) {
        gather_atomsH<<<(N_ATOMS + 3) / 4, vblk>>>(msgH, w_bonds, a2b, amsgH, MSGH);
        bond_updateH <<<(N_BONDS + 3) / 4, vblk>>>(amsgH, msgH, w_bonds, b2a, b2revb, tmpH);
        // msgH = relu(inp + tmp @ W_h)                         nCh = 10
        hgemm300<<<gridBonds, blk, SMEM_BYTES>>>(tmpH, MSGH, WhT, MSGH,
                                                 msgH, MSGH, nullptr,
                                                 inp, nullptr, nullptr, N_BONDS, 10, 1);
    }

    // final gather writes fp16 amsg straight into cat cols [0,300)
    gather_atomsH<<<(N_ATOMS + 3) / 4, vblk>>>(msgH, w_bonds, a2b, catH, CATH);

    // ah(fp32) = relu([amsg | f_atoms] @ WoC + b_o)            nCh = 14
    hgemm300<<<gridAtoms, blk, SMEM_BYTES>>>(catH, CATH, WoT, CATH,
                                             nullptr, 0, ah,
                                             nullptr, b_o, nullptr, N_ATOMS, 14, 1);

    readout4<<<(N_MOLS + 3) / 4, vblk>>>(
        (const float4*)ah, w_atoms, dop, (float4*)out);
}